// round 16
// baseline (speedup 1.0000x reference)
#include <cuda_runtime.h>
#include <math.h>
#include <stdint.h>

#define CC 10

static const int BLOCK = 256;
static const int GRID  = 296;      // 2 blocks per SM
static const int WPB   = 8;
static const int NWARPS = GRID * WPB;   // 2368
// stage tile = 128 rows = 320 float4 = 5KB; double-buffered per warp
static const int TILE_F4 = 320;
static const int SMEM_BYTES = WPB * 2 * TILE_F4 * 16;   // 81920

// Per-block partials: 0..9 sum p, 10..19 sum p^2, 20..29 sum v, 30 sum logsumexp
__device__ double g_partials[GRID][32];
__device__ unsigned int g_ticket = 0;

// ---------------------------------------------------------------------------
__device__ __forceinline__ uint32_t smem_u32(const void* p) {
    uint32_t a;
    asm("{ .reg .u64 t; cvta.to.shared.u64 t, %1; cvt.u32.u64 %0, t; }"
        : "=r"(a) : "l"(p));
    return a;
}
__device__ __forceinline__ void cp16(uint32_t s, const void* g) {
    asm volatile("cp.async.cg.shared.global [%0], [%1], 16;" :: "r"(s), "l"(g));
}
#define CP_COMMIT() asm volatile("cp.async.commit_group;")
#define CP_WAIT1()  asm volatile("cp.async.wait_group 1;")

// ---------------------------------------------------------------------------
// Fused branchless digamma + trigamma (shift to x+6 + asymptotic series).
// ---------------------------------------------------------------------------
__device__ __forceinline__ void psi01(float x, float& dg, float& tg) {
    float s0 = 0.f, s1 = 0.f;
#pragma unroll
    for (int k = 0; k < 6; k++) {
        float r = __fdividef(1.f, x + (float)k);
        s0 += r;
        s1  = fmaf(r, r, s1);
    }
    float y  = x + 6.f;
    float r  = __fdividef(1.f, y);
    float r2 = r * r;
    dg = __logf(y) - 0.5f * r
       - r2 * (0.0833333333f - r2 * (0.0083333333f - r2 * 0.0039682540f))
       - s0;
    tg = r + 0.5f * r2
       + r * r2 * (0.1666666667f - r2 * (0.0333333333f - r2 * 0.0238095238f))
       + s1;
}

__device__ __forceinline__ void allred2_16(float& v1, float& v2) {
#pragma unroll
    for (int o = 8; o > 0; o >>= 1) {
        v1 += __shfl_xor_sync(0xffffffffu, v1, o);
        v2 += __shfl_xor_sync(0xffffffffu, v2, o);
    }
}
__device__ __forceinline__ float allred1_16(float v) {
#pragma unroll
    for (int o = 8; o > 0; o >>= 1) v += __shfl_xor_sync(0xffffffffu, v, o);
    return v;
}

// ---------------------------------------------------------------------------
// Single kernel: stats (2-stage cp.async, 128-row tiles = 2 subtiles consumed
// per wait) + ticketed solve tail in the last-arriving block.
// ---------------------------------------------------------------------------
__global__ __launch_bounds__(256) void ed_fused(const float* __restrict__ x,
                                                float* __restrict__ out, int n) {
    extern __shared__ float4 stage[];   // [WPB][2][TILE_F4]

    const int lane = threadIdx.x & 31;
    const int w    = threadIdx.x >> 5;
    const int gw   = blockIdx.x * WPB + w;

    float ap [CC], ap2[CC], sv[CC];
    float sM = 0.f;
#pragma unroll
    for (int i = 0; i < CC; i++) { ap[i] = 0.f; ap2[i] = 0.f; sv[i] = 0.f; }

    const float4* __restrict__ x4 = reinterpret_cast<const float4*>(x);
    const int nT = n >> 7;              // 128-row tiles (15625 for n = 2M)

    float4* buf0 = stage + (w * 2    ) * TILE_F4;
    float4* buf1 = stage + (w * 2 + 1) * TILE_F4;
    const uint32_t sb0 = smem_u32(buf0);
    const uint32_t sb1 = smem_u32(buf1);

    int t = gw;
    if (t < nT) {
        const float4* src = x4 + (size_t)t * TILE_F4;
#pragma unroll
        for (int j = 0; j < 10; j++)
            cp16(sb0 + (uint32_t)(lane + j * 32) * 16u, src + lane + j * 32);
    }
    CP_COMMIT();

    int cur = 0;
    for (; t < nT; t += NWARPS) {
        const int t2 = t + NWARPS;
        const uint32_t sbn = cur ? sb0 : sb1;
        if (t2 < nT) {
            const float4* src = x4 + (size_t)t2 * TILE_F4;
#pragma unroll
            for (int j = 0; j < 10; j++)
                cp16(sbn + (uint32_t)(lane + j * 32) * 16u, src + lane + j * 32);
        }
        CP_COMMIT();
        CP_WAIT1();
        __syncwarp();

        const float4* b = cur ? buf1 : buf0;
        // two 64-row subtiles, each with the proven conflict-free layout
#pragma unroll
        for (int s = 0; s < 2; s++) {
            const float4* bs = b + s * 160;
            float4 q0 = bs[lane * 5    ];
            float4 q1 = bs[lane * 5 + 1];
            float4 q2 = bs[lane * 5 + 2];
            float4 q3 = bs[lane * 5 + 3];
            float4 q4 = bs[lane * 5 + 4];

            float v0[CC] = { q0.x, q0.y, q0.z, q0.w, q1.x, q1.y, q1.z, q1.w, q2.x, q2.y };
            float v1[CC] = { q2.z, q2.w, q3.x, q3.y, q3.z, q3.w, q4.x, q4.y, q4.z, q4.w };

            float e0[CC], e1[CC];
#pragma unroll
            for (int i = 0; i < CC; i++) { e0[i] = __expf(v0[i]); e1[i] = __expf(v1[i]); }

            float s0 = ((e0[0]+e0[1]) + (e0[2]+e0[3])) + ((e0[4]+e0[5]) + (e0[6]+e0[7])) + (e0[8]+e0[9]);
            float s1 = ((e1[0]+e1[1]) + (e1[2]+e1[3])) + ((e1[4]+e1[5]) + (e1[6]+e1[7])) + (e1[8]+e1[9]);

            float inv0 = __fdividef(1.f, s0);
            float inv1 = __fdividef(1.f, s1);
            sM += __logf(s0 * s1);

#pragma unroll
            for (int i = 0; i < CC; i++) {
                float p0 = e0[i] * inv0;
                float p1 = e1[i] * inv1;
                ap [i] += p0 + p1;
                ap2[i]  = fmaf(p0, p0, ap2[i]);
                ap2[i]  = fmaf(p1, p1, ap2[i]);
                sv [i] += v0[i] + v1[i];
            }
        }

        __syncwarp();
        cur ^= 1;
    }

    // tail rows (none for n % 128 == 0, kept for generality)
    for (int r0 = (nT << 7) + blockIdx.x * blockDim.x + threadIdx.x; r0 < n;
         r0 += gridDim.x * blockDim.x) {
        const float2* row = reinterpret_cast<const float2*>(x) + r0 * 5;
        float v[CC];
#pragma unroll
        for (int j = 0; j < 5; j++) { float2 t2 = row[j]; v[2*j] = t2.x; v[2*j+1] = t2.y; }
        float e[CC], s = 0.f;
#pragma unroll
        for (int i = 0; i < CC; i++) { e[i] = __expf(v[i]); s += e[i]; }
        float inv = __fdividef(1.f, s);
        sM += __logf(s);
#pragma unroll
        for (int i = 0; i < CC; i++) {
            float p = e[i] * inv;
            ap[i] += p; ap2[i] = fmaf(p, p, ap2[i]); sv[i] += v[i];
        }
    }

    // ---- block reduction: 31 stats -> double partials ----
#pragma unroll
    for (int i = 0; i < CC; i++) {
#pragma unroll
        for (int o = 16; o > 0; o >>= 1) {
            ap [i] += __shfl_down_sync(0xffffffffu, ap [i], o);
            ap2[i] += __shfl_down_sync(0xffffffffu, ap2[i], o);
            sv [i] += __shfl_down_sync(0xffffffffu, sv [i], o);
        }
    }
#pragma unroll
    for (int o = 16; o > 0; o >>= 1) sM += __shfl_down_sync(0xffffffffu, sM, o);

    __shared__ float sh[31][WPB];
    if (lane == 0) {
#pragma unroll
        for (int i = 0; i < CC; i++) {
            sh[i     ][w] = ap [i];
            sh[10 + i][w] = ap2[i];
            sh[20 + i][w] = sv [i];
        }
        sh[30][w] = sM;
    }
    __syncthreads();
    if (threadIdx.x < 31) {
        double s2 = 0.0;
#pragma unroll
        for (int w2 = 0; w2 < WPB; w2++) s2 += (double)sh[threadIdx.x][w2];
        g_partials[blockIdx.x][threadIdx.x] = s2;
    }

    // ---------------- ticketed tail: last block solves ----------------------
    __shared__ bool amLast;
    __threadfence();
    if (threadIdx.x == 0) {
        unsigned int tk = atomicAdd(&g_ticket, 1u);
        amLast = (tk == (unsigned int)(gridDim.x - 1));
    }
    __syncthreads();
    if (!amLast) return;

    if (threadIdx.x == 0) g_ticket = 0;   // reset for next graph replay

    __shared__ double st[32];
    {
        const int stat = threadIdx.x >> 3, j = threadIdx.x & 7;
        double s = 0.0;
#pragma unroll 4
        for (int b = j; b < GRID; b += 8) s += g_partials[b][stat];
        s += __shfl_down_sync(0xffffffffu, s, 4, 8);
        s += __shfl_down_sync(0xffffffffu, s, 2, 8);
        s += __shfl_down_sync(0xffffffffu, s, 1, 8);
        if (j == 0) st[stat] = s;
    }
    __syncthreads();

    if (threadIdx.x < 32) {
        const int  l   = threadIdx.x;
        const bool act = (l < CC);
        const double dn = (double)n;

        float m1  = act ? (float)(st[l]      / dn) : 0.f;
        float m2  = act ? (float)(st[10 + l] / dn) : 0.f;
        float lpa = act ? (float)((st[20 + l] - st[30]) / dn) : 0.f;

        float ratio = act ? (m1 - m2) / (m2 - m1 * m1) : 0.f;
        float rmean = allred1_16(ratio) * 0.1f;
        float a     = act ? m1 * rmean : 0.f;
        float asum  = allred1_16(a);
        if (!act) { a = 1.0f; asum = 20.0f; }

#pragma unroll 1
        for (int k = 0; k < 10; k++) {
            float dga, tga, dgs, tgs;
            psi01(a,    dga, tga);
            psi01(asum, dgs, tgs);
            float g    = dgs - dga + lpa;
            float qinv = __fdividef(-1.f, tga);
            float num  = act ? g * qinv : 0.f;
            float qs   = act ? qinv     : 0.f;
            allred2_16(num, qs);
            float zinv = __fdividef(1.f, tgs);
            float b    = num / (zinv + qs);
            a    = act ? a - (g - b) * qinv : 1.0f;
            asum = act ? asum - (num - b * qs) : 20.0f;
        }
        if (act) out[l] = a;
    }
}

// ---------------------------------------------------------------------------
extern "C" void kernel_launch(void* const* d_in, const int* in_sizes, int n_in,
                              void* d_out, int out_size) {
    const float* x = (const float*)d_in[0];
    const int n = in_sizes[0] / CC;   // 2,000,000 rows

    static bool attrSet = false;      // host-side attribute, idempotent
    if (!attrSet) {
        cudaFuncSetAttribute(ed_fused, cudaFuncAttributeMaxDynamicSharedMemorySize,
                             SMEM_BYTES);
        attrSet = true;
    }
    ed_fused<<<GRID, BLOCK, SMEM_BYTES>>>(x, (float*)d_out, n);
}

// round 17
// speedup vs baseline: 1.1722x; 1.1722x over previous
#include <cuda_runtime.h>
#include <math.h>
#include <stdint.h>

#define CC 10

static const int BLOCK = 256;
static const int GRID  = 296;      // 2 blocks per SM
static const int WPB   = 8;
static const int NWARPS = GRID * WPB;   // 2368

// Per-block partials: 0..9 sum p, 10..19 sum p^2, 20..29 sum v, 30 sum logsumexp
__device__ double g_partials[GRID][32];
__device__ unsigned int g_ticket = 0;

// ---------------------------------------------------------------------------
__device__ __forceinline__ uint32_t smem_u32(const void* p) {
    uint32_t a;
    asm("{ .reg .u64 t; cvta.to.shared.u64 t, %1; cvt.u32.u64 %0, t; }"
        : "=r"(a) : "l"(p));
    return a;
}
__device__ __forceinline__ void cp16(uint32_t s, const void* g) {
    asm volatile("cp.async.cg.shared.global [%0], [%1], 16;" :: "r"(s), "l"(g));
}
#define CP_COMMIT() asm volatile("cp.async.commit_group;")
#define CP_WAIT1()  asm volatile("cp.async.wait_group 1;")

// ---- packed f32x2 helpers (sm_103a: FFMA2/FADD2/FMUL2 only via PTX) -------
__device__ __forceinline__ uint64_t pk2(float lo, float hi) {
    uint64_t r; asm("mov.b64 %0, {%1, %2};" : "=l"(r) : "f"(lo), "f"(hi)); return r;
}
__device__ __forceinline__ void upk2(uint64_t p, float& lo, float& hi) {
    asm("mov.b64 {%0, %1}, %2;" : "=f"(lo), "=f"(hi) : "l"(p));
}
__device__ __forceinline__ uint64_t add2_(uint64_t a, uint64_t b) {
    uint64_t r; asm("add.rn.f32x2 %0, %1, %2;" : "=l"(r) : "l"(a), "l"(b)); return r;
}
__device__ __forceinline__ uint64_t mul2_(uint64_t a, uint64_t b) {
    uint64_t r; asm("mul.rn.f32x2 %0, %1, %2;" : "=l"(r) : "l"(a), "l"(b)); return r;
}
__device__ __forceinline__ uint64_t fma2_(uint64_t a, uint64_t b, uint64_t c) {
    uint64_t r; asm("fma.rn.f32x2 %0, %1, %2, %3;" : "=l"(r) : "l"(a), "l"(b), "l"(c)); return r;
}

// ---------------------------------------------------------------------------
// Fused branchless digamma + trigamma (shift to x+6 + asymptotic series).
// ---------------------------------------------------------------------------
__device__ __forceinline__ void psi01(float x, float& dg, float& tg) {
    float s0 = 0.f, s1 = 0.f;
#pragma unroll
    for (int k = 0; k < 6; k++) {
        float r = __fdividef(1.f, x + (float)k);
        s0 += r;
        s1  = fmaf(r, r, s1);
    }
    float y  = x + 6.f;
    float r  = __fdividef(1.f, y);
    float r2 = r * r;
    dg = __logf(y) - 0.5f * r
       - r2 * (0.0833333333f - r2 * (0.0083333333f - r2 * 0.0039682540f))
       - s0;
    tg = r + 0.5f * r2
       + r * r2 * (0.1666666667f - r2 * (0.0333333333f - r2 * 0.0238095238f))
       + s1;
}

__device__ __forceinline__ void allred2_16(float& v1, float& v2) {
#pragma unroll
    for (int o = 8; o > 0; o >>= 1) {
        v1 += __shfl_xor_sync(0xffffffffu, v1, o);
        v2 += __shfl_xor_sync(0xffffffffu, v2, o);
    }
}
__device__ __forceinline__ float allred1_16(float v) {
#pragma unroll
    for (int o = 8; o > 0; o >>= 1) v += __shfl_xor_sync(0xffffffffu, v, o);
    return v;
}

// ---------------------------------------------------------------------------
// Single kernel: stats (2-stage cp.async, packed f32x2 accumulation) +
// ticketed solve tail in the last-arriving block.
// ---------------------------------------------------------------------------
__global__ __launch_bounds__(256) void ed_fused(const float* __restrict__ x,
                                                float* __restrict__ out, int n) {
    __shared__ float4 stage[WPB][2][160];   // 40KB

    const int lane = threadIdx.x & 31;
    const int w    = threadIdx.x >> 5;
    const int gw   = blockIdx.x * WPB + w;

    // packed accumulators: 5 channel-pairs each for sum p, sum p^2, sum v
    uint64_t apP[5], ap2P[5], svP[5];
    const uint64_t z2 = pk2(0.f, 0.f);
#pragma unroll
    for (int j = 0; j < 5; j++) { apP[j] = z2; ap2P[j] = z2; svP[j] = z2; }
    float sM = 0.f;

    const float4* __restrict__ x4 = reinterpret_cast<const float4*>(x);
    const int nT = n >> 6;

    const uint32_t sb0 = smem_u32(&stage[w][0][0]);
    const uint32_t sb1 = smem_u32(&stage[w][1][0]);

    int t = gw;
    if (t < nT) {
        const float4* src = x4 + (size_t)t * 160;
#pragma unroll
        for (int j = 0; j < 5; j++)
            cp16(sb0 + (uint32_t)(lane + j * 32) * 16u, src + lane + j * 32);
    }
    CP_COMMIT();

    int cur = 0;
    for (; t < nT; t += NWARPS) {
        const int t2 = t + NWARPS;
        const uint32_t sbn = cur ? sb0 : sb1;
        if (t2 < nT) {
            const float4* src = x4 + (size_t)t2 * 160;
#pragma unroll
            for (int j = 0; j < 5; j++)
                cp16(sbn + (uint32_t)(lane + j * 32) * 16u, src + lane + j * 32);
        }
        CP_COMMIT();
        CP_WAIT1();
        __syncwarp();

        const float4* b = &stage[w][cur][0];
        float4 q0 = b[lane * 5    ];
        float4 q1 = b[lane * 5 + 1];
        float4 q2 = b[lane * 5 + 2];
        float4 q3 = b[lane * 5 + 3];
        float4 q4 = b[lane * 5 + 4];

        float v0[CC] = { q0.x, q0.y, q0.z, q0.w, q1.x, q1.y, q1.z, q1.w, q2.x, q2.y };
        float v1[CC] = { q2.z, q2.w, q3.x, q3.y, q3.z, q3.w, q4.x, q4.y, q4.z, q4.w };

        // 20 independent scalar exps (MUFU)
        float e0[CC], e1[CC];
#pragma unroll
        for (int i = 0; i < CC; i++) { e0[i] = __expf(v0[i]); e1[i] = __expf(v1[i]); }

        // pack channel pairs (2j, 2j+1) for both rows
        uint64_t e0P[5], e1P[5], v0P[5], v1P[5];
#pragma unroll
        for (int j = 0; j < 5; j++) {
            e0P[j] = pk2(e0[2*j], e0[2*j+1]);
            e1P[j] = pk2(e1[2*j], e1[2*j+1]);
            v0P[j] = pk2(v0[2*j], v0[2*j+1]);
            v1P[j] = pk2(v1[2*j], v1[2*j+1]);
        }

        // packed sum trees -> (s_even, s_odd) -> scalar s
        uint64_t t0a = add2_(e0P[0], e0P[1]);
        uint64_t t0b = add2_(e0P[2], e0P[3]);
        uint64_t t0c = add2_(add2_(t0a, t0b), e0P[4]);
        float s0lo, s0hi; upk2(t0c, s0lo, s0hi);
        float s0 = s0lo + s0hi;

        uint64_t t1a = add2_(e1P[0], e1P[1]);
        uint64_t t1b = add2_(e1P[2], e1P[3]);
        uint64_t t1c = add2_(add2_(t1a, t1b), e1P[4]);
        float s1lo, s1hi; upk2(t1c, s1lo, s1hi);
        float s1 = s1lo + s1hi;

        float inv0 = __fdividef(1.f, s0);
        float inv1 = __fdividef(1.f, s1);
        sM += __logf(s0 * s1);

        uint64_t inv0P = pk2(inv0, inv0);
        uint64_t inv1P = pk2(inv1, inv1);

#pragma unroll
        for (int j = 0; j < 5; j++) {
            uint64_t p0 = mul2_(e0P[j], inv0P);
            uint64_t p1 = mul2_(e1P[j], inv1P);
            apP [j] = add2_(apP[j], add2_(p0, p1));
            ap2P[j] = fma2_(p0, p0, ap2P[j]);
            ap2P[j] = fma2_(p1, p1, ap2P[j]);
            svP [j] = add2_(svP[j], add2_(v0P[j], v1P[j]));
        }

        __syncwarp();
        cur ^= 1;
    }

    // unpack packed accumulators into scalar arrays
    float ap[CC], ap2[CC], sv[CC];
#pragma unroll
    for (int j = 0; j < 5; j++) {
        upk2(apP [j], ap [2*j], ap [2*j+1]);
        upk2(ap2P[j], ap2[2*j], ap2[2*j+1]);
        upk2(svP [j], sv [2*j], sv [2*j+1]);
    }

    // tail rows (none for n % 64 == 0, kept for generality)
    for (int r0 = (nT << 6) + blockIdx.x * blockDim.x + threadIdx.x; r0 < n;
         r0 += gridDim.x * blockDim.x) {
        const float2* row = reinterpret_cast<const float2*>(x) + r0 * 5;
        float v[CC];
#pragma unroll
        for (int j = 0; j < 5; j++) { float2 t2 = row[j]; v[2*j] = t2.x; v[2*j+1] = t2.y; }
        float e[CC], s = 0.f;
#pragma unroll
        for (int i = 0; i < CC; i++) { e[i] = __expf(v[i]); s += e[i]; }
        float inv = __fdividef(1.f, s);
        sM += __logf(s);
#pragma unroll
        for (int i = 0; i < CC; i++) {
            float p = e[i] * inv;
            ap[i] += p; ap2[i] = fmaf(p, p, ap2[i]); sv[i] += v[i];
        }
    }

    // ---- block reduction: 31 stats -> double partials ----
#pragma unroll
    for (int i = 0; i < CC; i++) {
#pragma unroll
        for (int o = 16; o > 0; o >>= 1) {
            ap [i] += __shfl_down_sync(0xffffffffu, ap [i], o);
            ap2[i] += __shfl_down_sync(0xffffffffu, ap2[i], o);
            sv [i] += __shfl_down_sync(0xffffffffu, sv [i], o);
        }
    }
#pragma unroll
    for (int o = 16; o > 0; o >>= 1) sM += __shfl_down_sync(0xffffffffu, sM, o);

    __shared__ float sh[31][WPB];
    if (lane == 0) {
#pragma unroll
        for (int i = 0; i < CC; i++) {
            sh[i     ][w] = ap [i];
            sh[10 + i][w] = ap2[i];
            sh[20 + i][w] = sv [i];
        }
        sh[30][w] = sM;
    }
    __syncthreads();
    if (threadIdx.x < 31) {
        double s2 = 0.0;
#pragma unroll
        for (int w2 = 0; w2 < WPB; w2++) s2 += (double)sh[threadIdx.x][w2];
        g_partials[blockIdx.x][threadIdx.x] = s2;
    }

    // ---------------- ticketed tail: last block solves ----------------------
    __shared__ bool amLast;
    __threadfence();
    if (threadIdx.x == 0) {
        unsigned int tk = atomicAdd(&g_ticket, 1u);
        amLast = (tk == (unsigned int)(gridDim.x - 1));
    }
    __syncthreads();
    if (!amLast) return;

    if (threadIdx.x == 0) g_ticket = 0;   // reset for next graph replay

    __shared__ double st[32];
    {
        const int stat = threadIdx.x >> 3, j = threadIdx.x & 7;
        double s = 0.0;
#pragma unroll 4
        for (int b = j; b < GRID; b += 8) s += g_partials[b][stat];
        s += __shfl_down_sync(0xffffffffu, s, 4, 8);
        s += __shfl_down_sync(0xffffffffu, s, 2, 8);
        s += __shfl_down_sync(0xffffffffu, s, 1, 8);
        if (j == 0) st[stat] = s;
    }
    __syncthreads();

    if (threadIdx.x < 32) {
        const int  l   = threadIdx.x;
        const bool act = (l < CC);
        const double dn = (double)n;

        float m1  = act ? (float)(st[l]      / dn) : 0.f;
        float m2  = act ? (float)(st[10 + l] / dn) : 0.f;
        float lpa = act ? (float)((st[20 + l] - st[30]) / dn) : 0.f;

        float ratio = act ? (m1 - m2) / (m2 - m1 * m1) : 0.f;
        float rmean = allred1_16(ratio) * 0.1f;
        float a     = act ? m1 * rmean : 0.f;
        float asum  = allred1_16(a);
        if (!act) { a = 1.0f; asum = 20.0f; }

#pragma unroll 1
        for (int k = 0; k < 10; k++) {
            float dga, tga, dgs, tgs;
            psi01(a,    dga, tga);
            psi01(asum, dgs, tgs);
            float g    = dgs - dga + lpa;
            float qinv = __fdividef(-1.f, tga);
            float num  = act ? g * qinv : 0.f;
            float qs   = act ? qinv     : 0.f;
            allred2_16(num, qs);
            float zinv = __fdividef(1.f, tgs);
            float b    = num / (zinv + qs);
            a    = act ? a - (g - b) * qinv : 1.0f;
            asum = act ? asum - (num - b * qs) : 20.0f;
        }
        if (act) out[l] = a;
    }
}

// ---------------------------------------------------------------------------
extern "C" void kernel_launch(void* const* d_in, const int* in_sizes, int n_in,
                              void* d_out, int out_size) {
    const float* x = (const float*)d_in[0];
    const int n = in_sizes[0] / CC;   // 2,000,000 rows
    ed_fused<<<GRID, BLOCK>>>(x, (float*)d_out, n);
}